// round 9
// baseline (speedup 1.0000x reference)
#include <cuda_runtime.h>
#include <math.h>

// Problem constants
#define N_SAMPLES 32768
#define N_FRAMES  128
#define STEP      (N_SAMPLES / N_FRAMES)   // 256
#define N_FREQS   16
#define POS_DIM   (2 * N_FREQS + 1)        // 33
#define MODEL_DIM 128
#define N_ROWS    512                      // B * N_EVENTS = 32 * 16

#define PI_D 3.14159265358979323846

// ---------------------------------------------------------------------------
// COMPILE-TIME positional-encoding table, stored TRANSPOSED: posT[j][f]
// so the per-frame dot (thread = frame) reads consecutive floats across the
// warp. Same double-precision recurrence that passed R6-R8 with identical
// argmaxes (abs err ~3e-10, 200x below half an f32 ulp).
// ---------------------------------------------------------------------------
struct PosTableT { float v[POS_DIM * N_FRAMES]; };   // [j][f]

constexpr double csin_core(double x) {            // |x| <= pi
    double x2 = x * x, term = x, sum = x;
    for (int k = 1; k <= 25; k++) {
        term *= -x2 / (double)((2 * k) * (2 * k + 1));
        sum += term;
    }
    return sum;
}
constexpr double ccos_core(double x) {            // |x| <= pi
    double x2 = x * x, term = 1.0, sum = 1.0;
    for (int k = 1; k <= 25; k++) {
        term *= -x2 / (double)((2 * k - 1) * (2 * k));
        sum += term;
    }
    return sum;
}
constexpr double csqrt_d(double x) {              // Newton, x > 0
    double g = x > 1.0 ? x : 1.0;
    for (int i = 0; i < 80; i++) g = 0.5 * (g + x / g);
    return g;
}

constexpr PosTableT make_pos_table_T() {
    PosTableT T{};
    for (int f = 0; f < N_FRAMES; f++) {
        double xd = -PI_D + (double)f * (2.0 * PI_D / 127.0);
        float x = (float)xd;

        double s = csin_core((double)x);
        double c = ccos_core((double)x);

        float feat[POS_DIM] = {};
        feat[0] = x;
        for (int i = 0; i < N_FREQS; i++) {
            feat[1 + 2 * i] = (float)s;           // sin(2^i * x)
            feat[2 + 2 * i] = (float)c;           // cos(2^i * x)
            double s2 = 2.0 * s * c;
            double c2 = 1.0 - 2.0 * s * s;
            s = s2; c = c2;
        }
        float nrm = 0.0f;
        for (int j = 0; j < POS_DIM; j++) nrm += feat[j] * feat[j];
        float inv = 1.0f / ((float)csqrt_d((double)nrm) + 1e-8f);
        for (int j = 0; j < POS_DIM; j++) T.v[j * N_FRAMES + f] = feat[j] * inv;
    }
    return T;
}

constexpr PosTableT kPosT = make_pos_table_T();    // compile-time
__device__ const PosTableT g_posT = kPosT;

// ---------------------------------------------------------------------------
// Single fused kernel. grid (4, 512), 256 threads.
//
// Prelude (redundant, 4 blocks/row — ~1K cycles, overlapped across the 4
// resident CTAs per SM):
//   p = time_latent[row] @ W + b   (33 outputs, single-accumulator, same
//                                   summation order as all passing rounds)
//   sim_f = p . posn_f             (thread f, coalesced transposed table;
//                                   p's norm is a positive scalar: argmax-
//                                   invariant, skipped)
//   block argmax (ties -> lowest index) -> d = 256 * argmax
//
// Streaming (the 128MB that matters):
//   out[row,t] = (t >= d) ? stems[row, t-d] / 256 : 0
//   Each thread front-batches 8 independent float4 loads (MLP_p1=8):
//   4 CTAs/SM x 8 warps x 8 = 256 in-flight LDG.128 per SM.
//   d is a multiple of 256 -> all float4 accesses stay 16B-aligned.
// ---------------------------------------------------------------------------
#define CHUNK 8192    // samples per block = 256 threads * 8 float4
#define NLD   8       // float4 loads per thread

__global__ void __launch_bounds__(256) fused_kernel(
        const float* __restrict__ tl,
        const float* __restrict__ W,
        const float* __restrict__ b,
        const float* __restrict__ stems,
        float* __restrict__ out) {
    const int row = blockIdx.y;
    const int tid = threadIdx.x;   // 0..255

    __shared__ float s_tl[MODEL_DIM];
    __shared__ float s_p[POS_DIM];
    __shared__ float s_val[N_FRAMES];
    __shared__ int   s_idx[N_FRAMES];
    __shared__ int   s_delay;

    // ---- prelude: compute this row's delay ----
    if (tid < MODEL_DIM) s_tl[tid] = tl[row * MODEL_DIM + tid];
    __syncthreads();

    if (tid < POS_DIM) {
        float acc = 0.0f;
#pragma unroll 8
        for (int k = 0; k < MODEL_DIM; k++)
            acc += s_tl[k] * W[k * POS_DIM + tid];   // W is (128, 33) row-major
        s_p[tid] = acc + b[tid];
    }
    __syncthreads();

    if (tid < N_FRAMES) {
        float dot = 0.0f;
#pragma unroll
        for (int j = 0; j < POS_DIM; j++)
            dot += s_p[j] * g_posT.v[j * N_FRAMES + tid];   // coalesced in tid
        s_val[tid] = dot;
        s_idx[tid] = tid;
    }
    __syncthreads();

    for (int s = 64; s > 0; s >>= 1) {
        if (tid < s) {
            float vu = s_val[tid + s];
            int   iu = s_idx[tid + s];
            if (vu > s_val[tid] || (vu == s_val[tid] && iu < s_idx[tid])) {
                s_val[tid] = vu;
                s_idx[tid] = iu;
            }
        }
        __syncthreads();
    }
    if (tid == 0) s_delay = s_idx[0] * STEP;
    __syncthreads();

    // ---- streaming: shifted copy with scale ----
    const int d = s_delay;
    const float SCALE = 1.0f / 256.0f;   // 1/sqrt(2*N_SAMPLES), exact pow2

    const float* src = stems + (size_t)row * N_SAMPLES;
    float* dstf      = out   + (size_t)row * N_SAMPLES;
    const int base   = blockIdx.x * CHUNK + tid * 4;

    float4 v[NLD];
#pragma unroll
    for (int i = 0; i < NLD; i++) v[i] = make_float4(0.f, 0.f, 0.f, 0.f);

    // Front-batch all 8 independent loads
#pragma unroll
    for (int i = 0; i < NLD; i++) {
        int t = base + i * 1024;         // 256 threads * 4 floats
        if (t >= d)
            v[i] = *reinterpret_cast<const float4*>(src + (t - d));
    }

#pragma unroll
    for (int i = 0; i < NLD; i++) {
        v[i].x *= SCALE; v[i].y *= SCALE; v[i].z *= SCALE; v[i].w *= SCALE;
        int t = base + i * 1024;
        *reinterpret_cast<float4*>(dstf + t) = v[i];
    }
}

// ---------------------------------------------------------------------------
extern "C" void kernel_launch(void* const* d_in, const int* in_sizes, int n_in,
                              void* d_out, int out_size) {
    // metadata order: time_latent, stems, targets (unused), W, b
    const float* tl    = (const float*)d_in[0];
    const float* stems = (const float*)d_in[1];
    const float* W     = (const float*)d_in[3];
    const float* b     = (const float*)d_in[4];
    float* out = (float*)d_out;

    dim3 grid(N_SAMPLES / CHUNK, N_ROWS);   // (4, 512)
    fused_kernel<<<grid, 256>>>(tl, W, b, stems, out);
}

// round 11
// speedup vs baseline: 1.6497x; 1.6497x over previous
#include <cuda_runtime.h>
#include <math.h>

// Problem constants
#define N_SAMPLES 32768
#define N_FRAMES  128
#define STEP      (N_SAMPLES / N_FRAMES)   // 256
#define N_FREQS   16
#define POS_DIM   (2 * N_FREQS + 1)        // 33
#define MODEL_DIM 128
#define N_ROWS    512                      // B * N_EVENTS = 32 * 16

#define PI_D 3.14159265358979323846

// ---------------------------------------------------------------------------
// COMPILE-TIME positional-encoding table, stored TRANSPOSED: posT[j][f] so
// the per-frame dot (thread = frame f) is fully coalesced. Same double-
// precision recurrence that passed R6-R9 with identical argmaxes.
// ---------------------------------------------------------------------------
struct PosTableT { float v[POS_DIM * N_FRAMES]; };   // [j][f]

constexpr double csin_core(double x) {            // |x| <= pi
    double x2 = x * x, term = x, sum = x;
    for (int k = 1; k <= 25; k++) {
        term *= -x2 / (double)((2 * k) * (2 * k + 1));
        sum += term;
    }
    return sum;
}
constexpr double ccos_core(double x) {            // |x| <= pi
    double x2 = x * x, term = 1.0, sum = 1.0;
    for (int k = 1; k <= 25; k++) {
        term *= -x2 / (double)((2 * k - 1) * (2 * k));
        sum += term;
    }
    return sum;
}
constexpr double csqrt_d(double x) {              // Newton, x > 0
    double g = x > 1.0 ? x : 1.0;
    for (int i = 0; i < 80; i++) g = 0.5 * (g + x / g);
    return g;
}

constexpr PosTableT make_pos_table_T() {
    PosTableT T{};
    for (int f = 0; f < N_FRAMES; f++) {
        double xd = -PI_D + (double)f * (2.0 * PI_D / 127.0);
        float x = (float)xd;

        double s = csin_core((double)x);
        double c = ccos_core((double)x);

        float feat[POS_DIM] = {};
        feat[0] = x;
        for (int i = 0; i < N_FREQS; i++) {
            feat[1 + 2 * i] = (float)s;           // sin(2^i * x)
            feat[2 + 2 * i] = (float)c;           // cos(2^i * x)
            double s2 = 2.0 * s * c;
            double c2 = 1.0 - 2.0 * s * s;
            s = s2; c = c2;
        }
        float nrm = 0.0f;
        for (int j = 0; j < POS_DIM; j++) nrm += feat[j] * feat[j];
        float inv = 1.0f / ((float)csqrt_d((double)nrm) + 1e-8f);
        for (int j = 0; j < POS_DIM; j++) T.v[j * N_FRAMES + f] = feat[j] * inv;
    }
    return T;
}

constexpr PosTableT kPosT = make_pos_table_T();    // compile-time
__device__ const PosTableT g_posT = kPosT;

__device__ int g_delay[N_ROWS];

// ---------------------------------------------------------------------------
// Kernel 1: per-row delay. 512 blocks x 128 threads.
//  - W staged into shared via a coalesced cooperative load: the GEMV's 16
//    dependent batches hit LDS (29cyc) instead of L2 (~250cyc).
//  - Dot uses the TRANSPOSED table: coalesced (the non-transposed version
//    was ~32-way sector-replayed — the hidden ~10us tax in R8).
//  - All f32 summation orders identical to every passing round.
// ---------------------------------------------------------------------------
__global__ void __launch_bounds__(128) argmax_kernel(
        const float* __restrict__ tl,
        const float* __restrict__ W,
        const float* __restrict__ b) {
    int row = blockIdx.x;
    int tid = threadIdx.x;   // 0..127

    __shared__ float s_W[MODEL_DIM * POS_DIM];   // 16.5 KB
    __shared__ float s_tl[MODEL_DIM];
    __shared__ float s_p[POS_DIM];
    __shared__ float s_val[N_FRAMES];
    __shared__ int   s_idx[N_FRAMES];

    s_tl[tid] = tl[row * MODEL_DIM + tid];
    // coalesced stage of W (128*33 = 4224 floats, 33 per thread)
#pragma unroll
    for (int i = 0; i < POS_DIM; i++)
        s_W[i * MODEL_DIM + tid] = W[i * MODEL_DIM + tid];
    __syncthreads();

    if (tid < POS_DIM) {
        float acc = 0.0f;
#pragma unroll 8
        for (int k = 0; k < MODEL_DIM; k++)
            acc += s_tl[k] * s_W[k * POS_DIM + tid];   // same k-order as always
        s_p[tid] = acc + b[tid];
    }
    __syncthreads();

    float dot = 0.0f;
#pragma unroll
    for (int j = 0; j < POS_DIM; j++)
        dot += s_p[j] * g_posT.v[j * N_FRAMES + tid];  // coalesced in tid
    s_val[tid] = dot;
    s_idx[tid] = tid;
    __syncthreads();

    // argmax; exact tie -> lower index (matches jnp.argmax)
    for (int s = 64; s > 0; s >>= 1) {
        if (tid < s) {
            float vu = s_val[tid + s];
            int   iu = s_idx[tid + s];
            if (vu > s_val[tid] || (vu == s_val[tid] && iu < s_idx[tid])) {
                s_val[tid] = vu;
                s_idx[tid] = iu;
            }
        }
        __syncthreads();
    }
    if (tid == 0) g_delay[row] = s_idx[0] * STEP;
}

// ---------------------------------------------------------------------------
// Kernel 2: delta convolution == shift. The 128MB streaming phase.
//   out[row,t] = (t >= d) ? stems[row, t-d] / 256 : 0
// grid (8, 512) = 4096 blocks x 256 threads, 4 front-batched independent
// float4 loads per thread (R8's MLP=2 left DRAM at 38% / issue 21% —
// latency-bound, so raise in-flight sectors). Streaming stores (__stcs)
// keep the never-re-read output from evicting stems out of L2.
// d is a multiple of 256 -> float4 stays 16B-aligned on both sides.
// ---------------------------------------------------------------------------
#define NLD   4
#define CHUNK (256 * 4 * NLD)   // 4096 samples per block

__global__ void __launch_bounds__(256) shift_kernel(
        const float* __restrict__ stems,
        float* __restrict__ out) {
    const int row  = blockIdx.y;
    const int tid  = threadIdx.x;
    const int base = blockIdx.x * CHUNK + tid * 4;
    const int d    = g_delay[row];

    const float SCALE = 1.0f / 256.0f;   // 1/sqrt(2*N_SAMPLES), exact pow2

    const float* src = stems + (size_t)row * N_SAMPLES;
    float* dstf      = out   + (size_t)row * N_SAMPLES;

    float4 v[NLD];
#pragma unroll
    for (int i = 0; i < NLD; i++) v[i] = make_float4(0.f, 0.f, 0.f, 0.f);

    // front-batch all independent loads
#pragma unroll
    for (int i = 0; i < NLD; i++) {
        int t = base + i * 1024;         // 256 threads * 4 floats
        if (t >= d)
            v[i] = *reinterpret_cast<const float4*>(src + (t - d));
    }

#pragma unroll
    for (int i = 0; i < NLD; i++) {
        v[i].x *= SCALE; v[i].y *= SCALE; v[i].z *= SCALE; v[i].w *= SCALE;
        int t = base + i * 1024;
        __stcs(reinterpret_cast<float4*>(dstf + t), v[i]);   // streaming store
    }
}

// ---------------------------------------------------------------------------
extern "C" void kernel_launch(void* const* d_in, const int* in_sizes, int n_in,
                              void* d_out, int out_size) {
    // metadata order: time_latent, stems, targets (unused), W, b
    const float* tl    = (const float*)d_in[0];
    const float* stems = (const float*)d_in[1];
    const float* W     = (const float*)d_in[3];
    const float* b     = (const float*)d_in[4];
    float* out = (float*)d_out;

    argmax_kernel<<<N_ROWS, 128>>>(tl, W, b);

    dim3 grid(N_SAMPLES / CHUNK, N_ROWS);   // (8, 512)
    shift_kernel<<<grid, 256>>>(stems, out);
}